// round 3
// baseline (speedup 1.0000x reference)
#include <cuda_runtime.h>
#include <math.h>

#define BB 4
#define CC 128
#define HH 128
#define WW 240
#define EE 64
#define RNG 4
#define KK 9          // 2*RNG+1
#define HW (HH*WW)    // 30720

// Scratch: normalized embeddings, layout [tensor][b][h][w][e] with e contiguous.
__device__ __align__(16) float g_emb[2][(size_t)BB * HW * EE];

// ---------------------------------------------------------------------------
// Packed fp32x2 helpers (sm_100+ f32x2 pipe; ptxas never emits these from C++)
// ---------------------------------------------------------------------------
__device__ __forceinline__ unsigned long long pack2(float lo, float hi) {
    unsigned long long r;
    asm("mov.b64 %0, {%1, %2};" : "=l"(r) : "f"(lo), "f"(hi));
    return r;
}
__device__ __forceinline__ void ffma2(unsigned long long& d,
                                      unsigned long long a,
                                      unsigned long long b) {
    asm("fma.rn.f32x2 %0, %1, %2, %0;" : "+l"(d) : "l"(a), "l"(b));
}
__device__ __forceinline__ float lo32(unsigned long long v) {
    return __uint_as_float((unsigned)v);
}
__device__ __forceinline__ float hi32(unsigned long long v) {
    return __uint_as_float((unsigned)(v >> 32));
}

// ---------------------------------------------------------------------------
// Embed: y[e] = sum_c phi[e][c] * F[b][c][h][w]; L2-normalize; store [b][q][e].
// One thread per pixel; 32 packed f32x2 accumulators; phi transposed in smem
// so E-pairs are contiguous ([c][e], read as ulonglong2 -> LDS.128 broadcast).
// ---------------------------------------------------------------------------
__global__ __launch_bounds__(256)
void embed_kernel(const float* __restrict__ FL,
                  const float* __restrict__ FR,
                  const float* __restrict__ phi)
{
    __shared__ __align__(16) float phi_sm[CC * EE];   // [c][e], 32 KB

    const int t = threadIdx.x;
    for (int i = t; i < CC * EE; i += 256) {
        const int e = i >> 7;           // phi is [e][c]
        const int c = i & 127;
        phi_sm[c * EE + e] = phi[i];    // transpose to [c][e]
    }
    __syncthreads();

    const int q = blockIdx.x * 256 + t;
    if (q >= HW) return;
    const int b      = blockIdx.y;
    const int tensor = blockIdx.z;

    const float* __restrict__ F =
        (tensor == 0 ? FL : FR) + (size_t)b * CC * HW + q;

    unsigned long long acc[EE / 2];
#pragma unroll
    for (int i = 0; i < EE / 2; i++) acc[i] = 0ULL;

    const ulonglong2* __restrict__ ph =
        reinterpret_cast<const ulonglong2*>(phi_sm);

#pragma unroll 4
    for (int c = 0; c < CC; c++) {
        const float f = __ldg(&F[c * HW]);
        const unsigned long long bf = pack2(f, f);
        const ulonglong2* __restrict__ row = ph + c * (EE / 4);
#pragma unroll
        for (int j = 0; j < EE / 4; j++) {     // 16 x LDS.128, 32 x FFMA2
            const ulonglong2 p = row[j];
            ffma2(acc[2 * j + 0], p.x, bf);
            ffma2(acc[2 * j + 1], p.y, bf);
        }
    }

    float s = 0.0f;
#pragma unroll
    for (int i = 0; i < EE / 2; i++) {
        const float x = lo32(acc[i]);
        const float y = hi32(acc[i]);
        s = fmaf(x, x, s);
        s = fmaf(y, y, s);
    }
    const float inv = 1.0f / (sqrtf(s) + 1e-6f);

    float4* __restrict__ outp =
        reinterpret_cast<float4*>(&g_emb[tensor][((size_t)b * HW + q) * EE]);
#pragma unroll
    for (int j = 0; j < EE / 4; j++) {
        float4 v;
        v.x = lo32(acc[2 * j + 0]) * inv;
        v.y = hi32(acc[2 * j + 0]) * inv;
        v.z = lo32(acc[2 * j + 1]) * inv;
        v.w = hi32(acc[2 * j + 1]) * inv;
        outp[j] = v;
    }
}

// ---------------------------------------------------------------------------
// Correlation: warp split into two 16-lane groups; each group owns one pixel,
// lanes span E as float4 (contiguous 256B gathers -> ~4 wavefronts/warp-load).
// 9 taps reduced with 4 shfl.bfly steps each.
// ---------------------------------------------------------------------------
__global__ __launch_bounds__(256)
void corr_kernel(const float* __restrict__ d0,
                 float* __restrict__ out)
{
    const int h  = blockIdx.x;
    const int b  = blockIdx.y;
    const int wi = threadIdx.x >> 5;          // warp 0..7
    const int lane = threadIdx.x & 31;
    const int half = lane >> 4;               // 0/1: which pixel of the pair
    const int sub  = lane & 15;               // lane within 16-group (E chunk)

    const float* __restrict__ fr_row =
        &g_emb[1][((size_t)b * HW + (size_t)h * WW) * EE];
    const float* __restrict__ fl_row =
        &g_emb[0][((size_t)b * HW + (size_t)h * WW) * EE];
    const float* __restrict__ d_row = d0 + (size_t)b * HW + (size_t)h * WW;

    const int wbase = wi * (WW / 8);          // 30 pixels per warp

#pragma unroll 1
    for (int it = 0; it < (WW / 8) / 2; it++) {
        const int w = wbase + 2 * it + half;

        // FL vector chunk for this pixel: 16 lanes x float4 = 64 floats
        const float4 fl =
            reinterpret_cast<const float4*>(&fl_row[(size_t)w * EE])[sub];
        const float d = d_row[w];

        float partial[KK];
#pragma unroll
        for (int k = 0; k < KK; k++) {
            const float xp   = (float)w - d - (float)(k - RNG);
            const float x0   = floorf(xp);
            const float frac = xp - x0;
            int i0 = (int)x0;
            int i1 = i0 + 1;
            i0 = min(max(i0, 0), WW - 1);
            i1 = min(max(i1, 0), WW - 1);

            const float4 a =
                reinterpret_cast<const float4*>(&fr_row[(size_t)i0 * EE])[sub];
            const float4 c =
                reinterpret_cast<const float4*>(&fr_row[(size_t)i1 * EE])[sub];

            float dot = 0.0f;
            float v;
            v = fmaf(frac, c.x - a.x, a.x); dot = fmaf(fl.x, v, dot);
            v = fmaf(frac, c.y - a.y, a.y); dot = fmaf(fl.y, v, dot);
            v = fmaf(frac, c.z - a.z, a.z); dot = fmaf(fl.z, v, dot);
            v = fmaf(frac, c.w - a.w, a.w); dot = fmaf(fl.w, v, dot);
            partial[k] = dot;
        }

        // Reduce each tap over the 16-lane group (xor 8,4,2,1 stays in-group)
#pragma unroll
        for (int k = 0; k < KK; k++) {
            float p = partial[k];
            p += __shfl_xor_sync(0xffffffffu, p, 8);
            p += __shfl_xor_sync(0xffffffffu, p, 4);
            p += __shfl_xor_sync(0xffffffffu, p, 2);
            p += __shfl_xor_sync(0xffffffffu, p, 1);
            partial[k] = p;
        }

        // Lane `sub` (0..8) writes tap `sub` — static selection, no local mem
        float v = partial[0];
#pragma unroll
        for (int k = 1; k < KK; k++)
            if (sub == k) v = partial[k];
        if (sub < KK)
            out[(((size_t)b * KK + sub) * HH + h) * WW + w] = v;
    }
}

extern "C" void kernel_launch(void* const* d_in, const int* in_sizes, int n_in,
                              void* d_out, int out_size)
{
    const float* F_L   = (const float*)d_in[0];
    const float* F_R   = (const float*)d_in[1];
    const float* d0    = (const float*)d_in[2];
    const float* phi_w = (const float*)d_in[3];
    float* out = (float*)d_out;

    {
        dim3 grid((HW + 255) / 256, BB, 2);
        embed_kernel<<<grid, 256>>>(F_L, F_R, phi_w);
    }
    {
        dim3 grid(HH, BB, 1);
        corr_kernel<<<grid, 256>>>(d0, out);
    }
}

// round 4
// speedup vs baseline: 2.6486x; 2.6486x over previous
#include <cuda_runtime.h>
#include <cuda_bf16.h>
#include <math.h>

#define BB 4
#define CC 128
#define HH 128
#define WW 240
#define EE 64
#define RNG 4
#define KK 9          // 2*RNG+1
#define HW (HH*WW)    // 30720
#define EPSN 1e-6f

// Normalized embeddings, [tensor][b][q][e], e contiguous. 63 MB (fits L2).
__device__ __align__(16) float g_emb[2][(size_t)BB * HW * EE];

// phi in mma-fragment order: [ktile(8)][ntile(8)][lane(32)] -> uint4
// (b0_hi, b1_hi, b0_lo, b1_lo) bf16x2 words. 32 KB, L1/L2-resident.
__device__ uint4 g_phi_frag[8 * 8 * 32];

// ---------------------------------------------------------------------------
// mma.sync m16n8k16 row.col f32.bf16.bf16.f32
// ---------------------------------------------------------------------------
__device__ __forceinline__ void mma_bf16(float& d0, float& d1, float& d2, float& d3,
                                         unsigned a0, unsigned a1, unsigned a2, unsigned a3,
                                         unsigned b0, unsigned b1)
{
    asm volatile(
        "mma.sync.aligned.m16n8k16.row.col.f32.bf16.bf16.f32 "
        "{%0,%1,%2,%3}, {%4,%5,%6,%7}, {%8,%9}, {%0,%1,%2,%3};\n"
        : "+f"(d0), "+f"(d1), "+f"(d2), "+f"(d3)
        : "r"(a0), "r"(a1), "r"(a2), "r"(a3), "r"(b0), "r"(b1));
}

__device__ __forceinline__ unsigned pack_bf16x2(__nv_bfloat16 lo, __nv_bfloat16 hi)
{
    unsigned short l = __bfloat16_as_ushort(lo);
    unsigned short h = __bfloat16_as_ushort(hi);
    return (unsigned)l | ((unsigned)h << 16);
}

__device__ __forceinline__ void split_bf16(float x, __nv_bfloat16& hi, __nv_bfloat16& lo)
{
    hi = __float2bfloat16_rn(x);
    lo = __float2bfloat16_rn(x - __bfloat162float(hi));
}

// ---------------------------------------------------------------------------
// prep_phi: build B fragments for all (ktile, ntile, lane).
// B[k=c][n=e] = phi[e][c]. m16n8k16 .col B frag:
//   b0 = {B[2t][g], B[2t+1][g]},  b1 = {B[2t+8][g], B[2t+9][g]},
// g = lane>>2, t = lane&3.
// ---------------------------------------------------------------------------
__global__ void prep_phi_kernel(const float* __restrict__ phi)
{
    const int idx = blockIdx.x * blockDim.x + threadIdx.x;   // 0..2047
    if (idx >= 8 * 8 * 32) return;
    const int lane = idx & 31;
    const int nt   = (idx >> 5) & 7;
    const int kt   = idx >> 8;
    const int g    = lane >> 2;
    const int t    = lane & 3;

    const int e  = nt * 8 + g;
    const int c0 = kt * 16 + 2 * t;

    const float x0 = phi[e * CC + c0 + 0];
    const float x1 = phi[e * CC + c0 + 1];
    const float x2 = phi[e * CC + c0 + 8];
    const float x3 = phi[e * CC + c0 + 9];

    __nv_bfloat16 h0, l0, h1, l1, h2, l2, h3, l3;
    split_bf16(x0, h0, l0);
    split_bf16(x1, h1, l1);
    split_bf16(x2, h2, l2);
    split_bf16(x3, h3, l3);

    uint4 v;
    v.x = pack_bf16x2(h0, h1);   // b0_hi
    v.y = pack_bf16x2(h2, h3);   // b1_hi
    v.z = pack_bf16x2(l0, l1);   // b0_lo
    v.w = pack_bf16x2(l2, l3);   // b1_lo
    g_phi_frag[idx] = v;
}

// ---------------------------------------------------------------------------
// embed: per block 64 q-pixels x full E=64, K=C=128 via tensor cores.
// 4 warps, each warp one m16 tile. A tile transposed+bf16-split in smem.
// ---------------------------------------------------------------------------
#define QT 64                 // q tile per block
#define APAD_STRIDE 65        // ulonglong per q row (64 pairs + 1 pad)

__global__ __launch_bounds__(128)
void embed_kernel(const float* __restrict__ FL,
                  const float* __restrict__ FR,
                  float* __restrict__ /*unused*/ dummy)
{
    // A_s[q][pair p=c>>1] : 8 B = bf16{hi_even, hi_odd, lo_even, lo_odd}
    __shared__ __align__(16) unsigned long long A_s[QT * APAD_STRIDE];

    const int t      = threadIdx.x;
    const int qbase  = blockIdx.x * QT;
    const int b      = blockIdx.y;
    const int tensor = blockIdx.z;

    const float* __restrict__ F =
        (tensor == 0 ? FL : FR) + (size_t)b * CC * HW;

    // Load + transpose + split: 8192 elements, 64 per thread, coalesced in q.
    unsigned short* A_sh = reinterpret_cast<unsigned short*>(A_s);
#pragma unroll 8
    for (int it = 0; it < 64; it++) {
        const int linear = it * 128 + t;
        const int q = linear & 63;
        const int c = linear >> 6;
        const float x = __ldg(&F[(size_t)c * HW + qbase + q]);
        __nv_bfloat16 hi, lo;
        split_bf16(x, hi, lo);
        const int p = c >> 1, o = c & 1;
        const int base = (q * APAD_STRIDE + p) * 4;
        A_sh[base + o]     = __bfloat16_as_ushort(hi);
        A_sh[base + 2 + o] = __bfloat16_as_ushort(lo);
    }
    __syncthreads();

    const int warp = t >> 5;
    const int lane = t & 31;
    const int g    = lane >> 2;
    const int tg   = lane & 3;
    const int r0   = warp * 16 + g;       // A_s row for a0/a2
    const int r1   = r0 + 8;              // row for a1/a3

    float acc[8][4];
#pragma unroll
    for (int nt = 0; nt < 8; nt++)
#pragma unroll
        for (int i = 0; i < 4; i++) acc[nt][i] = 0.0f;

    const uint2* __restrict__ A2 = reinterpret_cast<const uint2*>(A_s);

#pragma unroll
    for (int kt = 0; kt < 8; kt++) {
        const int p = kt * 8 + tg;
        const uint2 v0 = A2[r0 * APAD_STRIDE + p];       // a0 hi/lo
        const uint2 v1 = A2[r1 * APAD_STRIDE + p];       // a1 hi/lo
        const uint2 v2 = A2[r0 * APAD_STRIDE + p + 4];   // a2 hi/lo
        const uint2 v3 = A2[r1 * APAD_STRIDE + p + 4];   // a3 hi/lo

        const uint4* __restrict__ Bf = &g_phi_frag[(kt * 8) * 32 + lane];
#pragma unroll
        for (int nt = 0; nt < 8; nt++) {
            const uint4 bf = Bf[nt * 32];
            // hi*hi
            mma_bf16(acc[nt][0], acc[nt][1], acc[nt][2], acc[nt][3],
                     v0.x, v1.x, v2.x, v3.x, bf.x, bf.y);
            // hi*lo
            mma_bf16(acc[nt][0], acc[nt][1], acc[nt][2], acc[nt][3],
                     v0.x, v1.x, v2.x, v3.x, bf.z, bf.w);
            // lo*hi
            mma_bf16(acc[nt][0], acc[nt][1], acc[nt][2], acc[nt][3],
                     v0.y, v1.y, v2.y, v3.y, bf.x, bf.y);
        }
    }

    // Normalize rows r0 (acc[.][0,1]) and r1 (acc[.][2,3]) over E.
    float s0 = 0.0f, s1 = 0.0f;
#pragma unroll
    for (int nt = 0; nt < 8; nt++) {
        s0 = fmaf(acc[nt][0], acc[nt][0], s0);
        s0 = fmaf(acc[nt][1], acc[nt][1], s0);
        s1 = fmaf(acc[nt][2], acc[nt][2], s1);
        s1 = fmaf(acc[nt][3], acc[nt][3], s1);
    }
    // Reduce across the 4-thread quad (same g): xor 1, 2.
    s0 += __shfl_xor_sync(0xffffffffu, s0, 1);
    s0 += __shfl_xor_sync(0xffffffffu, s0, 2);
    s1 += __shfl_xor_sync(0xffffffffu, s1, 1);
    s1 += __shfl_xor_sync(0xffffffffu, s1, 2);
    const float inv0 = 1.0f / (sqrtf(s0) + EPSN);
    const float inv1 = 1.0f / (sqrtf(s1) + EPSN);

    float* __restrict__ outT = g_emb[tensor];
    const size_t row0 = ((size_t)b * HW + qbase + r0) * EE;
    const size_t row1 = ((size_t)b * HW + qbase + r1) * EE;
#pragma unroll
    for (int nt = 0; nt < 8; nt++) {
        const int e = nt * 8 + 2 * tg;
        float2 w0; w0.x = acc[nt][0] * inv0; w0.y = acc[nt][1] * inv0;
        float2 w1; w1.x = acc[nt][2] * inv1; w1.y = acc[nt][3] * inv1;
        *reinterpret_cast<float2*>(&outT[row0 + e]) = w0;
        *reinterpret_cast<float2*>(&outT[row1 + e]) = w1;
    }
}

// ---------------------------------------------------------------------------
// corr: integer deltas => one shared frac, 10 consecutive FR columns.
// cost_k = (1-f)*s[8-k] + f*s[9-k],  s_j = dot(FL, FR[clamp(base+j)]).
// 16-lane group per pixel, lanes span E as float4.
// ---------------------------------------------------------------------------
__global__ __launch_bounds__(128)
void corr_kernel(const float* __restrict__ d0,
                 float* __restrict__ out)
{
    const int h    = blockIdx.x;
    const int b    = blockIdx.y;
    const int woff = blockIdx.z * (WW / 2);   // 0 or 120
    const int gid  = threadIdx.x >> 4;        // 8 groups
    const int sub  = threadIdx.x & 15;

    const float* __restrict__ fl_row =
        &g_emb[0][((size_t)b * HW + (size_t)h * WW) * EE];
    const float* __restrict__ fr_row =
        &g_emb[1][((size_t)b * HW + (size_t)h * WW) * EE];
    const float* __restrict__ d_row = d0 + (size_t)b * HW + (size_t)h * WW;

#pragma unroll 1
    for (int it = 0; it < 15; it++) {
        const int w = woff + gid + 8 * it;

        const float4 fl =
            reinterpret_cast<const float4*>(&fl_row[(size_t)w * EE])[sub];
        const float d  = __ldg(&d_row[w]);

        const float xf   = (float)w - d;
        const float f0f  = floorf(xf);
        const float frac = xf - f0f;
        const int base   = (int)f0f - RNG;

        float s[10];
#pragma unroll
        for (int j = 0; j < 10; j++) {
            const int idx = min(max(base + j, 0), WW - 1);
            const float4 fr =
                reinterpret_cast<const float4*>(&fr_row[(size_t)idx * EE])[sub];
            float dot;
            dot = fl.x * fr.x;
            dot = fmaf(fl.y, fr.y, dot);
            dot = fmaf(fl.z, fr.z, dot);
            dot = fmaf(fl.w, fr.w, dot);
            s[j] = dot;
        }

        // Reduce each s_j across the 16-lane group.
#pragma unroll
        for (int j = 0; j < 10; j++) {
            float p = s[j];
            p += __shfl_xor_sync(0xffffffffu, p, 8);
            p += __shfl_xor_sync(0xffffffffu, p, 4);
            p += __shfl_xor_sync(0xffffffffu, p, 2);
            p += __shfl_xor_sync(0xffffffffu, p, 1);
            s[j] = p;
        }

        // Lane `sub` emits tap k = sub: cost = (1-f)*s[8-sub] + f*s[9-sub].
        float sA = s[8], sB = s[9];
#pragma unroll
        for (int k = 1; k < KK; k++)
            if (sub == k) { sA = s[8 - k]; sB = s[9 - k]; }
        const float cost = sA * (1.0f - frac) + sB * frac;

        if (sub < KK)
            out[(((size_t)b * KK + sub) * HH + h) * WW + w] = cost;
    }
}

extern "C" void kernel_launch(void* const* d_in, const int* in_sizes, int n_in,
                              void* d_out, int out_size)
{
    const float* F_L   = (const float*)d_in[0];
    const float* F_R   = (const float*)d_in[1];
    const float* d0    = (const float*)d_in[2];
    const float* phi_w = (const float*)d_in[3];
    float* out = (float*)d_out;

    prep_phi_kernel<<<8, 256>>>(phi_w);

    {
        dim3 grid(HW / QT, BB, 2);           // 480 x 4 x 2
        embed_kernel<<<grid, 128>>>(F_L, F_R, nullptr);
    }
    {
        dim3 grid(HH, BB, 2);                // 1024 blocks
        corr_kernel<<<grid, 128>>>(d0, out);
    }
}

// round 5
// speedup vs baseline: 2.7129x; 1.0243x over previous
#include <cuda_runtime.h>
#include <cuda_bf16.h>
#include <math.h>

#define BB 4
#define CC 128
#define HH 128
#define WW 240
#define EE 64
#define RNG 4
#define KK 9          // 2*RNG+1
#define HW (HH*WW)    // 30720
#define EPSN 1e-6f

// Normalized embeddings, [tensor][b][q][e], e contiguous. 63 MB.
__device__ __align__(16) float g_emb[2][(size_t)BB * HW * EE];

// phi tf32 fragments: [kt(16)][nt(8)][lane(32)] -> uint4 (b0_hi,b1_hi,b0_lo,b1_lo).
// m16n8k8 .col B frag: b0 = B[lane%4][lane/4], b1 = B[lane%4+4][lane/4],
// with B[k=c][n=e] = phi[e][c]. 64 KB.
__device__ uint4 g_phi_frag[16 * 8 * 32];

// ---------------------------------------------------------------------------
// mma.sync m16n8k8 row.col f32.tf32.tf32.f32
// ---------------------------------------------------------------------------
__device__ __forceinline__ void mma_tf32(float& d0, float& d1, float& d2, float& d3,
                                         unsigned a0, unsigned a1, unsigned a2, unsigned a3,
                                         unsigned b0, unsigned b1)
{
    asm volatile(
        "mma.sync.aligned.m16n8k8.row.col.f32.tf32.tf32.f32 "
        "{%0,%1,%2,%3}, {%4,%5,%6,%7}, {%8,%9}, {%0,%1,%2,%3};\n"
        : "+f"(d0), "+f"(d1), "+f"(d2), "+f"(d3)
        : "r"(a0), "r"(a1), "r"(a2), "r"(a3), "r"(b0), "r"(b1));
}

__device__ __forceinline__ unsigned cvt_tf32_rna(float x)
{
    unsigned r;
    asm("cvt.rna.tf32.f32 %0, %1;" : "=r"(r) : "f"(x));
    return r;
}

// Round fp32 to tf32 grid (keep 10 explicit mantissa bits, round-nearest-ish).
__device__ __forceinline__ unsigned round_tf32_bits(float x)
{
    unsigned u = __float_as_uint(x);
    return (u + 0x1000u) & 0xFFFFE000u;
}

// ---------------------------------------------------------------------------
// prep_phi: build tf32 hi/lo B fragments.
// ---------------------------------------------------------------------------
__global__ void prep_phi_kernel(const float* __restrict__ phi)
{
    const int idx = blockIdx.x * blockDim.x + threadIdx.x;   // 0..4095
    if (idx >= 16 * 8 * 32) return;
    const int lane = idx & 31;
    const int nt   = (idx >> 5) & 7;
    const int kt   = idx >> 8;

    const int e  = nt * 8 + (lane >> 2);
    const int c0 = kt * 8 + (lane & 3);

    const float x0 = phi[e * CC + c0];
    const float x1 = phi[e * CC + c0 + 4];

    const unsigned h0 = cvt_tf32_rna(x0);
    const unsigned h1 = cvt_tf32_rna(x1);

    uint4 v;
    v.x = h0;
    v.y = h1;
    v.z = __float_as_uint(x0 - __uint_as_float(h0));
    v.w = __float_as_uint(x1 - __uint_as_float(h1));
    g_phi_frag[idx] = v;
}

// ---------------------------------------------------------------------------
// embed: 64 q-pixels per block, E=64, K=C=128 via tf32 MMA (2 products).
// A staged raw-rounded fp32 in smem [q][c], pad stride 133 (conflict-free).
// ---------------------------------------------------------------------------
#define QT 64
#define S_A 133

__global__ __launch_bounds__(128)
void embed_kernel(const float* __restrict__ FL,
                  const float* __restrict__ FR)
{
    __shared__ __align__(16) float A_s[QT * S_A];   // 34 KB

    const int t      = threadIdx.x;
    const int qbase  = blockIdx.x * QT;
    const int b      = blockIdx.y;
    const int tensor = blockIdx.z;

    const float* __restrict__ F =
        (tensor == 0 ? FL : FR) + (size_t)b * CC * HW;

    // Load 64x128 A tile: float4 loads along q, rounded to tf32 grid,
    // transposed store to [q][c].
#pragma unroll 4
    for (int it = 0; it < 16; it++) {
        const int idx = it * 128 + t;
        const int tq  = idx & 15;          // float4 index along q
        const int c   = idx >> 4;          // 0..127
        const float4 v = __ldg(reinterpret_cast<const float4*>(
                                   &F[(size_t)c * HW + qbase]) + tq);
        const int q0 = tq * 4;
        A_s[(q0 + 0) * S_A + c] = __uint_as_float(round_tf32_bits(v.x));
        A_s[(q0 + 1) * S_A + c] = __uint_as_float(round_tf32_bits(v.y));
        A_s[(q0 + 2) * S_A + c] = __uint_as_float(round_tf32_bits(v.z));
        A_s[(q0 + 3) * S_A + c] = __uint_as_float(round_tf32_bits(v.w));
    }
    __syncthreads();

    const int warp = t >> 5;
    const int lane = t & 31;
    const int g    = lane >> 2;
    const int tg   = lane & 3;
    const int r0   = warp * 16 + g;
    const int r1   = r0 + 8;

    float acc[8][4];
#pragma unroll
    for (int nt = 0; nt < 8; nt++)
#pragma unroll
        for (int i = 0; i < 4; i++) acc[nt][i] = 0.0f;

    const uint4* __restrict__ Bf = g_phi_frag + lane;

#pragma unroll
    for (int kt = 0; kt < 16; kt++) {
        const float* __restrict__ ar0 = &A_s[r0 * S_A + kt * 8 + tg];
        const float* __restrict__ ar1 = &A_s[r1 * S_A + kt * 8 + tg];
        const unsigned a0 = __float_as_uint(ar0[0]);
        const unsigned a2 = __float_as_uint(ar0[4]);
        const unsigned a1 = __float_as_uint(ar1[0]);
        const unsigned a3 = __float_as_uint(ar1[4]);

#pragma unroll
        for (int nt = 0; nt < 8; nt++) {
            const uint4 bf = Bf[(kt * 8 + nt) * 32];
            mma_tf32(acc[nt][0], acc[nt][1], acc[nt][2], acc[nt][3],
                     a0, a1, a2, a3, bf.x, bf.y);   // A * B_hi
            mma_tf32(acc[nt][0], acc[nt][1], acc[nt][2], acc[nt][3],
                     a0, a1, a2, a3, bf.z, bf.w);   // A * B_lo
        }
    }

    // Normalize rows r0 (acc[.][0,1]) and r1 (acc[.][2,3]) over E.
    float s0 = 0.0f, s1 = 0.0f;
#pragma unroll
    for (int nt = 0; nt < 8; nt++) {
        s0 = fmaf(acc[nt][0], acc[nt][0], s0);
        s0 = fmaf(acc[nt][1], acc[nt][1], s0);
        s1 = fmaf(acc[nt][2], acc[nt][2], s1);
        s1 = fmaf(acc[nt][3], acc[nt][3], s1);
    }
    s0 += __shfl_xor_sync(0xffffffffu, s0, 1);
    s0 += __shfl_xor_sync(0xffffffffu, s0, 2);
    s1 += __shfl_xor_sync(0xffffffffu, s1, 1);
    s1 += __shfl_xor_sync(0xffffffffu, s1, 2);
    const float inv0 = 1.0f / (sqrtf(s0) + EPSN);
    const float inv1 = 1.0f / (sqrtf(s1) + EPSN);

    float* __restrict__ outT = g_emb[tensor];
    const size_t row0 = ((size_t)b * HW + qbase + r0) * EE;
    const size_t row1 = ((size_t)b * HW + qbase + r1) * EE;
#pragma unroll
    for (int nt = 0; nt < 8; nt++) {
        const int e = nt * 8 + 2 * tg;
        float2 w0; w0.x = acc[nt][0] * inv0; w0.y = acc[nt][1] * inv0;
        float2 w1; w1.x = acc[nt][2] * inv1; w1.y = acc[nt][3] * inv1;
        *reinterpret_cast<float2*>(&outT[row0 + e]) = w0;
        *reinterpret_cast<float2*>(&outT[row1 + e]) = w1;
    }
}

// ---------------------------------------------------------------------------
// corr: one block per (h, b) row. FR row staged in dynamic smem (61.4 KB);
// gathers become conflict-free LDS.128. Shared-frac factorization:
// cost_k = (1-f)*s[8-k] + f*s[9-k],  s_j = dot(FL, FR[clamp(base+j)]).
// ---------------------------------------------------------------------------
__global__ __launch_bounds__(256)
void corr_kernel(const float* __restrict__ d0,
                 float* __restrict__ out)
{
    extern __shared__ __align__(16) float FR_s[];   // [240][64]

    const int h = blockIdx.x;
    const int b = blockIdx.y;
    const int t = threadIdx.x;

    const float* __restrict__ fl_row =
        &g_emb[0][((size_t)b * HW + (size_t)h * WW) * EE];
    const float* __restrict__ fr_row =
        &g_emb[1][((size_t)b * HW + (size_t)h * WW) * EE];
    const float* __restrict__ d_row = d0 + (size_t)b * HW + (size_t)h * WW;

    // Stage FR row: 15360 floats = 3840 float4, 15 per thread.
    {
        const float4* __restrict__ src = reinterpret_cast<const float4*>(fr_row);
        float4* __restrict__ dst = reinterpret_cast<float4*>(FR_s);
#pragma unroll
        for (int i = 0; i < 15; i++)
            dst[i * 256 + t] = __ldg(src + i * 256 + t);
    }
    __syncthreads();

    const int gid = t >> 4;        // 16 groups
    const int sub = t & 15;
    const float4* __restrict__ FR4 = reinterpret_cast<const float4*>(FR_s);

#pragma unroll 1
    for (int it = 0; it < 15; it++) {
        const int w = gid + 16 * it;

        const float4 fl =
            __ldg(reinterpret_cast<const float4*>(&fl_row[(size_t)w * EE]) + sub);
        const float d = __ldg(&d_row[w]);

        const float xf   = (float)w - d;
        const float f0f  = floorf(xf);
        const float frac = xf - f0f;
        const int base   = (int)f0f - RNG;

        float s[10];
#pragma unroll
        for (int j = 0; j < 10; j++) {
            const int idx = min(max(base + j, 0), WW - 1);
            const float4 fr = FR4[idx * 16 + sub];
            float dot;
            dot = fl.x * fr.x;
            dot = fmaf(fl.y, fr.y, dot);
            dot = fmaf(fl.z, fr.z, dot);
            dot = fmaf(fl.w, fr.w, dot);
            s[j] = dot;
        }

#pragma unroll
        for (int j = 0; j < 10; j++) {
            float p = s[j];
            p += __shfl_xor_sync(0xffffffffu, p, 8);
            p += __shfl_xor_sync(0xffffffffu, p, 4);
            p += __shfl_xor_sync(0xffffffffu, p, 2);
            p += __shfl_xor_sync(0xffffffffu, p, 1);
            s[j] = p;
        }

        float sA = s[8], sB = s[9];
#pragma unroll
        for (int k = 1; k < KK; k++)
            if (sub == k) { sA = s[8 - k]; sB = s[9 - k]; }
        const float cost = sA * (1.0f - frac) + sB * frac;

        if (sub < KK)
            out[(((size_t)b * KK + sub) * HH + h) * WW + w] = cost;
    }
}

extern "C" void kernel_launch(void* const* d_in, const int* in_sizes, int n_in,
                              void* d_out, int out_size)
{
    const float* F_L   = (const float*)d_in[0];
    const float* F_R   = (const float*)d_in[1];
    const float* d0    = (const float*)d_in[2];
    const float* phi_w = (const float*)d_in[3];
    float* out = (float*)d_out;

    const int corr_smem = WW * EE * (int)sizeof(float);   // 61440 B
    cudaFuncSetAttribute(corr_kernel,
                         cudaFuncAttributeMaxDynamicSharedMemorySize, corr_smem);

    prep_phi_kernel<<<16, 256>>>(phi_w);
    {
        dim3 grid(HW / QT, BB, 2);           // 480 x 4 x 2
        embed_kernel<<<grid, 128>>>(F_L, F_R);
    }
    {
        dim3 grid(HH, BB, 1);                // 512 blocks
        corr_kernel<<<grid, 256, corr_smem>>>(d0, out);
    }
}

// round 6
// speedup vs baseline: 2.8027x; 1.0331x over previous
#include <cuda_runtime.h>
#include <cuda_bf16.h>
#include <math.h>

#define BB 4
#define CC 128
#define HH 128
#define WW 240
#define EE 64
#define RNG 4
#define KK 9          // 2*RNG+1
#define HW (HH*WW)    // 30720
#define EPSN 1e-6f

// Normalized embeddings, [tensor][b][q][e], e contiguous. 63 MB.
__device__ __align__(16) float g_emb[2][(size_t)BB * HW * EE];

// phi tf32 fragments: [kt(16)][nt(8)][lane(32)] -> uint4 (b0_hi,b1_hi,b0_lo,b1_lo).
// m16n8k8 .col B frag: b0 = B[lane%4][lane/4], b1 = B[lane%4+4][lane/4],
// with B[k=c][n=e] = phi[e][c]. 64 KB, L1-resident.
__device__ uint4 g_phi_frag[16 * 8 * 32];

// ---------------------------------------------------------------------------
// mma.sync m16n8k8 row.col f32.tf32.tf32.f32
// ---------------------------------------------------------------------------
__device__ __forceinline__ void mma_tf32(float& d0, float& d1, float& d2, float& d3,
                                         unsigned a0, unsigned a1, unsigned a2, unsigned a3,
                                         unsigned b0, unsigned b1)
{
    asm volatile(
        "mma.sync.aligned.m16n8k8.row.col.f32.tf32.tf32.f32 "
        "{%0,%1,%2,%3}, {%4,%5,%6,%7}, {%8,%9}, {%0,%1,%2,%3};\n"
        : "+f"(d0), "+f"(d1), "+f"(d2), "+f"(d3)
        : "r"(a0), "r"(a1), "r"(a2), "r"(a3), "r"(b0), "r"(b1));
}

__device__ __forceinline__ unsigned cvt_tf32_rna(float x)
{
    unsigned r;
    asm("cvt.rna.tf32.f32 %0, %1;" : "=r"(r) : "f"(x));
    return r;
}

// Round fp32 to tf32 grid (10 explicit mantissa bits).
__device__ __forceinline__ unsigned round_tf32_bits(float x)
{
    unsigned u = __float_as_uint(x);
    return (u + 0x1000u) & 0xFFFFE000u;
}

// ---------------------------------------------------------------------------
// prep_phi: build tf32 hi/lo B fragments.
// ---------------------------------------------------------------------------
__global__ void prep_phi_kernel(const float* __restrict__ phi)
{
    const int idx = blockIdx.x * blockDim.x + threadIdx.x;   // 0..4095
    if (idx >= 16 * 8 * 32) return;
    const int lane = idx & 31;
    const int nt   = (idx >> 5) & 7;
    const int kt   = idx >> 8;

    const int e  = nt * 8 + (lane >> 2);
    const int c0 = kt * 8 + (lane & 3);

    const float x0 = phi[e * CC + c0];
    const float x1 = phi[e * CC + c0 + 4];

    const unsigned h0 = cvt_tf32_rna(x0);
    const unsigned h1 = cvt_tf32_rna(x1);

    uint4 v;
    v.x = h0;
    v.y = h1;
    v.z = __float_as_uint(x0 - __uint_as_float(h0));
    v.w = __float_as_uint(x1 - __uint_as_float(h1));
    g_phi_frag[idx] = v;
}

// ---------------------------------------------------------------------------
// embed: QT=128 q-pixels per block, E=64, K=C=128 via tf32 MMA (2 products).
// Each of 4 warps owns 2 m16-tiles; one B-frag load feeds 4 MMAs.
// A staged in smem [c][q] stride 136: STS.128 conflict-free stores,
// conflict-free LDS.32 frag reads (bank = 8*tg + g).
// ---------------------------------------------------------------------------
#define QT 128
#define S_A 136                  // floats per c-row (128 + 8 pad)

__global__ __launch_bounds__(128)
void embed_kernel(const float* __restrict__ FL,
                  const float* __restrict__ FR)
{
    extern __shared__ __align__(16) float A_s[];   // [CC][S_A] = 69632 B

    const int t      = threadIdx.x;
    const int qbase  = blockIdx.x * QT;
    const int b      = blockIdx.y;
    const int tensor = blockIdx.z;

    const float* __restrict__ F =
        (tensor == 0 ? FL : FR) + (size_t)b * CC * HW;

    // Load 128x128 A tile: float4 along q, tf32-round, store [c][q] via STS.128.
#pragma unroll 8
    for (int it = 0; it < 32; it++) {
        const int idx = it * 128 + t;
        const int tq  = idx & 31;          // float4 index along q
        const int c   = idx >> 5;          // 0..127
        const float4 v = __ldg(reinterpret_cast<const float4*>(
                                   &F[(size_t)c * HW + qbase]) + tq);
        float4 r;
        r.x = __uint_as_float(round_tf32_bits(v.x));
        r.y = __uint_as_float(round_tf32_bits(v.y));
        r.z = __uint_as_float(round_tf32_bits(v.z));
        r.w = __uint_as_float(round_tf32_bits(v.w));
        *reinterpret_cast<float4*>(&A_s[c * S_A + tq * 4]) = r;
    }
    __syncthreads();

    const int warp = t >> 5;
    const int lane = t & 31;
    const int g    = lane >> 2;
    const int tg   = lane & 3;

    // Two m-tiles per warp: rows m*16 + g and m*16 + g + 8, m = 2*warp + mt.
    float acc[2][8][4];
#pragma unroll
    for (int mt = 0; mt < 2; mt++)
#pragma unroll
        for (int nt = 0; nt < 8; nt++)
#pragma unroll
            for (int i = 0; i < 4; i++) acc[mt][nt][i] = 0.0f;

    const uint4* __restrict__ Bf = g_phi_frag + lane;
    const int r0 = (warp * 2) * 16 + g;       // mt=0 row
    const int r2 = (warp * 2 + 1) * 16 + g;   // mt=1 row

#pragma unroll
    for (int kt = 0; kt < 16; kt++) {
        const int k0 = kt * 8 + tg;
        unsigned a[2][4];
        a[0][0] = __float_as_uint(A_s[k0 * S_A + r0]);
        a[0][1] = __float_as_uint(A_s[k0 * S_A + r0 + 8]);
        a[0][2] = __float_as_uint(A_s[(k0 + 4) * S_A + r0]);
        a[0][3] = __float_as_uint(A_s[(k0 + 4) * S_A + r0 + 8]);
        a[1][0] = __float_as_uint(A_s[k0 * S_A + r2]);
        a[1][1] = __float_as_uint(A_s[k0 * S_A + r2 + 8]);
        a[1][2] = __float_as_uint(A_s[(k0 + 4) * S_A + r2]);
        a[1][3] = __float_as_uint(A_s[(k0 + 4) * S_A + r2 + 8]);

#pragma unroll
        for (int nt = 0; nt < 8; nt++) {
            const uint4 bf = Bf[(kt * 8 + nt) * 32];
#pragma unroll
            for (int mt = 0; mt < 2; mt++) {
                mma_tf32(acc[mt][nt][0], acc[mt][nt][1], acc[mt][nt][2], acc[mt][nt][3],
                         a[mt][0], a[mt][1], a[mt][2], a[mt][3], bf.x, bf.y); // A*B_hi
                mma_tf32(acc[mt][nt][0], acc[mt][nt][1], acc[mt][nt][2], acc[mt][nt][3],
                         a[mt][0], a[mt][1], a[mt][2], a[mt][3], bf.z, bf.w); // A*B_lo
            }
        }
    }

    // Normalize + store, per m-tile: rows r (acc[.][0,1]) and r+8 (acc[.][2,3]).
    float* __restrict__ outT = g_emb[tensor];
#pragma unroll
    for (int mt = 0; mt < 2; mt++) {
        const int r = (mt == 0 ? r0 : r2);
        float s0 = 0.0f, s1 = 0.0f;
#pragma unroll
        for (int nt = 0; nt < 8; nt++) {
            s0 = fmaf(acc[mt][nt][0], acc[mt][nt][0], s0);
            s0 = fmaf(acc[mt][nt][1], acc[mt][nt][1], s0);
            s1 = fmaf(acc[mt][nt][2], acc[mt][nt][2], s1);
            s1 = fmaf(acc[mt][nt][3], acc[mt][nt][3], s1);
        }
        s0 += __shfl_xor_sync(0xffffffffu, s0, 1);
        s0 += __shfl_xor_sync(0xffffffffu, s0, 2);
        s1 += __shfl_xor_sync(0xffffffffu, s1, 1);
        s1 += __shfl_xor_sync(0xffffffffu, s1, 2);
        const float inv0 = 1.0f / (sqrtf(s0) + EPSN);
        const float inv1 = 1.0f / (sqrtf(s1) + EPSN);

        const size_t row0 = ((size_t)b * HW + qbase + r) * EE;
        const size_t row1 = ((size_t)b * HW + qbase + r + 8) * EE;
#pragma unroll
        for (int nt = 0; nt < 8; nt++) {
            const int e = nt * 8 + 2 * tg;
            float2 w0; w0.x = acc[mt][nt][0] * inv0; w0.y = acc[mt][nt][1] * inv0;
            float2 w1; w1.x = acc[mt][nt][2] * inv1; w1.y = acc[mt][nt][3] * inv1;
            *reinterpret_cast<float2*>(&outT[row0 + e]) = w0;
            *reinterpret_cast<float2*>(&outT[row1 + e]) = w1;
        }
    }
}

// ---------------------------------------------------------------------------
// corr: one block per (h, b) row. FR row staged in dynamic smem (61.4 KB);
// gathers are conflict-free LDS.128. Shared-frac factorization:
// cost_k = (1-f)*s[8-k] + f*s[9-k],  s_j = dot(FL, FR[clamp(base+j)]).
// ---------------------------------------------------------------------------
__global__ __launch_bounds__(256)
void corr_kernel(const float* __restrict__ d0,
                 float* __restrict__ out)
{
    extern __shared__ __align__(16) float FR_s[];   // [240][64]

    const int h = blockIdx.x;
    const int b = blockIdx.y;
    const int t = threadIdx.x;

    const float* __restrict__ fl_row =
        &g_emb[0][((size_t)b * HW + (size_t)h * WW) * EE];
    const float* __restrict__ fr_row =
        &g_emb[1][((size_t)b * HW + (size_t)h * WW) * EE];
    const float* __restrict__ d_row = d0 + (size_t)b * HW + (size_t)h * WW;

    // Stage FR row: 15360 floats = 3840 float4, 15 per thread.
    {
        const float4* __restrict__ src = reinterpret_cast<const float4*>(fr_row);
        float4* __restrict__ dst = reinterpret_cast<float4*>(FR_s);
#pragma unroll
        for (int i = 0; i < 15; i++)
            dst[i * 256 + t] = __ldg(src + i * 256 + t);
    }
    __syncthreads();

    const int gid = t >> 4;        // 16 groups
    const int sub = t & 15;
    const float4* __restrict__ FR4 = reinterpret_cast<const float4*>(FR_s);

#pragma unroll 1
    for (int it = 0; it < 15; it++) {
        const int w = gid + 16 * it;

        const float4 fl =
            __ldg(reinterpret_cast<const float4*>(&fl_row[(size_t)w * EE]) + sub);
        const float d = __ldg(&d_row[w]);

        const float xf   = (float)w - d;
        const float f0f  = floorf(xf);
        const float frac = xf - f0f;
        const int base   = (int)f0f - RNG;

        float s[10];
#pragma unroll
        for (int j = 0; j < 10; j++) {
            const int idx = min(max(base + j, 0), WW - 1);
            const float4 fr = FR4[idx * 16 + sub];
            float dot;
            dot = fl.x * fr.x;
            dot = fmaf(fl.y, fr.y, dot);
            dot = fmaf(fl.z, fr.z, dot);
            dot = fmaf(fl.w, fr.w, dot);
            s[j] = dot;
        }

#pragma unroll
        for (int j = 0; j < 10; j++) {
            float p = s[j];
            p += __shfl_xor_sync(0xffffffffu, p, 8);
            p += __shfl_xor_sync(0xffffffffu, p, 4);
            p += __shfl_xor_sync(0xffffffffu, p, 2);
            p += __shfl_xor_sync(0xffffffffu, p, 1);
            s[j] = p;
        }

        float sA = s[8], sB = s[9];
#pragma unroll
        for (int k = 1; k < KK; k++)
            if (sub == k) { sA = s[8 - k]; sB = s[9 - k]; }
        const float cost = sA * (1.0f - frac) + sB * frac;

        if (sub < KK)
            out[(((size_t)b * KK + sub) * HH + h) * WW + w] = cost;
    }
}

extern "C" void kernel_launch(void* const* d_in, const int* in_sizes, int n_in,
                              void* d_out, int out_size)
{
    const float* F_L   = (const float*)d_in[0];
    const float* F_R   = (const float*)d_in[1];
    const float* d0    = (const float*)d_in[2];
    const float* phi_w = (const float*)d_in[3];
    float* out = (float*)d_out;

    const int embed_smem = CC * S_A * (int)sizeof(float);   // 69632 B
    const int corr_smem  = WW * EE * (int)sizeof(float);    // 61440 B
    cudaFuncSetAttribute(embed_kernel,
                         cudaFuncAttributeMaxDynamicSharedMemorySize, embed_smem);
    cudaFuncSetAttribute(corr_kernel,
                         cudaFuncAttributeMaxDynamicSharedMemorySize, corr_smem);

    prep_phi_kernel<<<16, 256>>>(phi_w);
    {
        dim3 grid(HW / QT, BB, 2);           // 240 x 4 x 2
        embed_kernel<<<grid, 128, embed_smem>>>(F_L, F_R);
    }
    {
        dim3 grid(HH, BB, 1);                // 512 blocks
        corr_kernel<<<grid, 256, corr_smem>>>(d0, out);
    }
}

// round 7
// speedup vs baseline: 3.4642x; 1.2360x over previous
#include <cuda_runtime.h>
#include <cuda_fp16.h>
#include <math.h>

#define BB 4
#define CC 128
#define HH 128
#define WW 240
#define EE 64
#define RNG 4
#define KK 9          // 2*RNG+1
#define HW (HH*WW)    // 30720
#define EPSN 1e-6f

// Normalized embeddings, fp16, [tensor][b][q][e], e contiguous. 31.5 MB.
__device__ __align__(16) __half g_emb[2][(size_t)BB * HW * EE];

// phi tf32 fragments: [kt(16)][nt(8)][lane(32)] -> uint4 (b0_hi,b1_hi,b0_lo,b1_lo).
__device__ uint4 g_phi_frag[16 * 8 * 32];

// ---------------------------------------------------------------------------
// mma.sync m16n8k8 row.col f32.tf32.tf32.f32
// ---------------------------------------------------------------------------
__device__ __forceinline__ void mma_tf32(float& d0, float& d1, float& d2, float& d3,
                                         unsigned a0, unsigned a1, unsigned a2, unsigned a3,
                                         unsigned b0, unsigned b1)
{
    asm volatile(
        "mma.sync.aligned.m16n8k8.row.col.f32.tf32.tf32.f32 "
        "{%0,%1,%2,%3}, {%4,%5,%6,%7}, {%8,%9}, {%0,%1,%2,%3};\n"
        : "+f"(d0), "+f"(d1), "+f"(d2), "+f"(d3)
        : "r"(a0), "r"(a1), "r"(a2), "r"(a3), "r"(b0), "r"(b1));
}

__device__ __forceinline__ unsigned cvt_tf32_rna(float x)
{
    unsigned r;
    asm("cvt.rna.tf32.f32 %0, %1;" : "=r"(r) : "f"(x));
    return r;
}

__device__ __forceinline__ unsigned round_tf32_bits(float x)
{
    unsigned u = __float_as_uint(x);
    return (u + 0x1000u) & 0xFFFFE000u;
}

__device__ __forceinline__ float2 h2f(unsigned u)
{
    __half2 h = *reinterpret_cast<__half2*>(&u);
    return __half22float2(h);
}

// ---------------------------------------------------------------------------
// prep_phi: tf32 hi/lo B fragments.
// ---------------------------------------------------------------------------
__global__ void prep_phi_kernel(const float* __restrict__ phi)
{
    const int idx = blockIdx.x * blockDim.x + threadIdx.x;   // 0..4095
    if (idx >= 16 * 8 * 32) return;
    const int lane = idx & 31;
    const int nt   = (idx >> 5) & 7;
    const int kt   = idx >> 8;

    const int e  = nt * 8 + (lane >> 2);
    const int c0 = kt * 8 + (lane & 3);

    const float x0 = phi[e * CC + c0];
    const float x1 = phi[e * CC + c0 + 4];

    const unsigned h0 = cvt_tf32_rna(x0);
    const unsigned h1 = cvt_tf32_rna(x1);

    uint4 v;
    v.x = h0;
    v.y = h1;
    v.z = __float_as_uint(x0 - __uint_as_float(h0));
    v.w = __float_as_uint(x1 - __uint_as_float(h1));
    g_phi_frag[idx] = v;
}

// ---------------------------------------------------------------------------
// embed: QT=128 pixels/block, tf32 MMA 2-product; fp16 output.
// ---------------------------------------------------------------------------
#define QT 128
#define S_A 136

__global__ __launch_bounds__(128)
void embed_kernel(const float* __restrict__ FL,
                  const float* __restrict__ FR)
{
    extern __shared__ __align__(16) float A_s[];   // [CC][S_A] = 69632 B

    const int t      = threadIdx.x;
    const int qbase  = blockIdx.x * QT;
    const int b      = blockIdx.y;
    const int tensor = blockIdx.z;

    const float* __restrict__ F =
        (tensor == 0 ? FL : FR) + (size_t)b * CC * HW;

#pragma unroll 8
    for (int it = 0; it < 32; it++) {
        const int idx = it * 128 + t;
        const int tq  = idx & 31;
        const int c   = idx >> 5;
        const float4 v = __ldg(reinterpret_cast<const float4*>(
                                   &F[(size_t)c * HW + qbase]) + tq);
        float4 r;
        r.x = __uint_as_float(round_tf32_bits(v.x));
        r.y = __uint_as_float(round_tf32_bits(v.y));
        r.z = __uint_as_float(round_tf32_bits(v.z));
        r.w = __uint_as_float(round_tf32_bits(v.w));
        *reinterpret_cast<float4*>(&A_s[c * S_A + tq * 4]) = r;
    }
    __syncthreads();

    const int warp = t >> 5;
    const int lane = t & 31;
    const int g    = lane >> 2;
    const int tg   = lane & 3;

    float acc[2][8][4];
#pragma unroll
    for (int mt = 0; mt < 2; mt++)
#pragma unroll
        for (int nt = 0; nt < 8; nt++)
#pragma unroll
            for (int i = 0; i < 4; i++) acc[mt][nt][i] = 0.0f;

    const uint4* __restrict__ Bf = g_phi_frag + lane;
    const int r0 = (warp * 2) * 16 + g;
    const int r2 = (warp * 2 + 1) * 16 + g;

#pragma unroll
    for (int kt = 0; kt < 16; kt++) {
        const int k0 = kt * 8 + tg;
        unsigned a[2][4];
        a[0][0] = __float_as_uint(A_s[k0 * S_A + r0]);
        a[0][1] = __float_as_uint(A_s[k0 * S_A + r0 + 8]);
        a[0][2] = __float_as_uint(A_s[(k0 + 4) * S_A + r0]);
        a[0][3] = __float_as_uint(A_s[(k0 + 4) * S_A + r0 + 8]);
        a[1][0] = __float_as_uint(A_s[k0 * S_A + r2]);
        a[1][1] = __float_as_uint(A_s[k0 * S_A + r2 + 8]);
        a[1][2] = __float_as_uint(A_s[(k0 + 4) * S_A + r2]);
        a[1][3] = __float_as_uint(A_s[(k0 + 4) * S_A + r2 + 8]);

#pragma unroll
        for (int nt = 0; nt < 8; nt++) {
            const uint4 bf = Bf[(kt * 8 + nt) * 32];
#pragma unroll
            for (int mt = 0; mt < 2; mt++) {
                mma_tf32(acc[mt][nt][0], acc[mt][nt][1], acc[mt][nt][2], acc[mt][nt][3],
                         a[mt][0], a[mt][1], a[mt][2], a[mt][3], bf.x, bf.y);
                mma_tf32(acc[mt][nt][0], acc[mt][nt][1], acc[mt][nt][2], acc[mt][nt][3],
                         a[mt][0], a[mt][1], a[mt][2], a[mt][3], bf.z, bf.w);
            }
        }
    }

    __half* __restrict__ outT = g_emb[tensor];
#pragma unroll
    for (int mt = 0; mt < 2; mt++) {
        const int r = (mt == 0 ? r0 : r2);
        float s0 = 0.0f, s1 = 0.0f;
#pragma unroll
        for (int nt = 0; nt < 8; nt++) {
            s0 = fmaf(acc[mt][nt][0], acc[mt][nt][0], s0);
            s0 = fmaf(acc[mt][nt][1], acc[mt][nt][1], s0);
            s1 = fmaf(acc[mt][nt][2], acc[mt][nt][2], s1);
            s1 = fmaf(acc[mt][nt][3], acc[mt][nt][3], s1);
        }
        s0 += __shfl_xor_sync(0xffffffffu, s0, 1);
        s0 += __shfl_xor_sync(0xffffffffu, s0, 2);
        s1 += __shfl_xor_sync(0xffffffffu, s1, 1);
        s1 += __shfl_xor_sync(0xffffffffu, s1, 2);
        const float inv0 = 1.0f / (sqrtf(s0) + EPSN);
        const float inv1 = 1.0f / (sqrtf(s1) + EPSN);

        const size_t row0 = ((size_t)b * HW + qbase + r) * EE;
        const size_t row1 = ((size_t)b * HW + qbase + r + 8) * EE;
#pragma unroll
        for (int nt = 0; nt < 8; nt++) {
            const int e = nt * 8 + 2 * tg;
            *reinterpret_cast<__half2*>(&outT[row0 + e]) =
                __floats2half2_rn(acc[mt][nt][0] * inv0, acc[mt][nt][1] * inv0);
            *reinterpret_cast<__half2*>(&outT[row1 + e]) =
                __floats2half2_rn(acc[mt][nt][2] * inv1, acc[mt][nt][3] * inv1);
        }
    }
}

// ---------------------------------------------------------------------------
// corr: fp16 embeddings; 8-lane groups (one uint4 = 8 halves per lane).
// FR row staged in smem (30 KB). Shared-frac factorization.
// ---------------------------------------------------------------------------
__global__ __launch_bounds__(256)
void corr_kernel(const float* __restrict__ d0,
                 float* __restrict__ out)
{
    extern __shared__ __align__(16) char FRC_s[];   // 240*64 halves = 30720 B

    const int h = blockIdx.x;
    const int b = blockIdx.y;
    const int t = threadIdx.x;

    const __half* __restrict__ fl_row =
        &g_emb[0][((size_t)b * HW + (size_t)h * WW) * EE];
    const __half* __restrict__ fr_row =
        &g_emb[1][((size_t)b * HW + (size_t)h * WW) * EE];
    const float* __restrict__ d_row = d0 + (size_t)b * HW + (size_t)h * WW;

    // Stage FR row: 1920 uint4.
    {
        const uint4* __restrict__ src = reinterpret_cast<const uint4*>(fr_row);
        uint4* __restrict__ dst = reinterpret_cast<uint4*>(FRC_s);
#pragma unroll
        for (int i = 0; i < 8; i++) {
            const int idx = i * 256 + t;
            if (idx < 1920) dst[idx] = __ldg(src + idx);
        }
    }
    __syncthreads();

    const int gid = t >> 3;        // 32 groups of 8 lanes
    const int sub = t & 7;
    const uint4* __restrict__ FR4 = reinterpret_cast<const uint4*>(FRC_s);

#pragma unroll 1
    for (int it = 0; it < 8; it++) {
        const int w = gid + 32 * it;
        const bool active = (w < WW);
        const int wс = active ? w : (WW - 1);

        // FL chunk: 8 halves -> fp32
        const uint4 flv =
            __ldg(reinterpret_cast<const uint4*>(&fl_row[(size_t)wс * EE]) + sub);
        const float2 fl0 = h2f(flv.x);
        const float2 fl1 = h2f(flv.y);
        const float2 fl2 = h2f(flv.z);
        const float2 fl3 = h2f(flv.w);

        const float d = __ldg(&d_row[wс]);
        const float xf   = (float)wс - d;
        const float f0f  = floorf(xf);
        const float frac = xf - f0f;
        const int base   = (int)f0f - RNG;

        float s[10];
#pragma unroll
        for (int j = 0; j < 10; j++) {
            const int idx = min(max(base + j, 0), WW - 1);
            const uint4 frv = FR4[idx * 8 + sub];
            const float2 a0 = h2f(frv.x);
            const float2 a1 = h2f(frv.y);
            const float2 a2 = h2f(frv.z);
            const float2 a3 = h2f(frv.w);
            float dot;
            dot = fl0.x * a0.x;
            dot = fmaf(fl0.y, a0.y, dot);
            dot = fmaf(fl1.x, a1.x, dot);
            dot = fmaf(fl1.y, a1.y, dot);
            dot = fmaf(fl2.x, a2.x, dot);
            dot = fmaf(fl2.y, a2.y, dot);
            dot = fmaf(fl3.x, a3.x, dot);
            dot = fmaf(fl3.y, a3.y, dot);
            s[j] = dot;
        }

#pragma unroll
        for (int j = 0; j < 10; j++) {
            float p = s[j];
            p += __shfl_xor_sync(0xffffffffu, p, 4);
            p += __shfl_xor_sync(0xffffffffu, p, 2);
            p += __shfl_xor_sync(0xffffffffu, p, 1);
            s[j] = p;
        }

        // Lane sub emits tap sub (0..7); lane 0 also emits tap 8.
        float sA = s[8], sB = s[9];
#pragma unroll
        for (int k = 1; k < 8; k++)
            if (sub == k) { sA = s[8 - k]; sB = s[9 - k]; }

        if (active) {
            const float omf = 1.0f - frac;
            out[(((size_t)b * KK + sub) * HH + h) * WW + w] = sA * omf + sB * frac;
            if (sub == 0)
                out[(((size_t)b * KK + 8) * HH + h) * WW + w] = s[0] * omf + s[1] * frac;
        }
    }
}

extern "C" void kernel_launch(void* const* d_in, const int* in_sizes, int n_in,
                              void* d_out, int out_size)
{
    const float* F_L   = (const float*)d_in[0];
    const float* F_R   = (const float*)d_in[1];
    const float* d0    = (const float*)d_in[2];
    const float* phi_w = (const float*)d_in[3];
    float* out = (float*)d_out;

    const int embed_smem = CC * S_A * (int)sizeof(float);      // 69632 B
    const int corr_smem  = WW * EE * (int)sizeof(__half);      // 30720 B
    cudaFuncSetAttribute(embed_kernel,
                         cudaFuncAttributeMaxDynamicSharedMemorySize, embed_smem);
    cudaFuncSetAttribute(corr_kernel,
                         cudaFuncAttributeMaxDynamicSharedMemorySize, corr_smem);

    prep_phi_kernel<<<16, 256>>>(phi_w);
    {
        dim3 grid(HW / QT, BB, 2);           // 240 x 4 x 2
        embed_kernel<<<grid, 128, embed_smem>>>(F_L, F_R);
    }
    {
        dim3 grid(HH, BB, 1);                // 512 blocks
        corr_kernel<<<grid, 256, corr_smem>>>(d0, out);
    }
}